// round 14
// baseline (speedup 1.0000x reference)
#include <cuda_runtime.h>
#include <cuda_bf16.h>
#include <cstdint>
#include <cstddef>

#define BB 2
#define TT 2048
#define DD 2048
#define HH 16
#define HDD 128
#define MROWS (BB*TT)   // 4096

// ---------------- scratch (static device globals; no runtime alloc) ----------------
// bf16 hi/lo splits
__device__ __nv_bfloat16 g_xhi[(size_t)MROWS * DD];
__device__ __nv_bfloat16 g_xlo[(size_t)MROWS * DD];
__device__ __nv_bfloat16 g_wqh[(size_t)3 * DD * DD];
__device__ __nv_bfloat16 g_wql[(size_t)3 * DD * DD];
__device__ __nv_bfloat16 g_woh[(size_t)DD * DD];
__device__ __nv_bfloat16 g_wol[(size_t)DD * DD];
__device__ __nv_bfloat16 g_ahi[(size_t)MROWS * DD];   // attn out (written by flash)
__device__ __nv_bfloat16 g_alo[(size_t)MROWS * DD];

// q/k/v hi-lo bf16, [B,H,T,HD]
#define QKVN ((size_t)BB * HH * TT * HDD)
__device__ __nv_bfloat16 g_qh[QKVN];
__device__ __nv_bfloat16 g_ql[QKVN];
__device__ __nv_bfloat16 g_kh[QKVN];
__device__ __nv_bfloat16 g_kl[QKVN];
__device__ __nv_bfloat16 g_vh[QKVN];
__device__ __nv_bfloat16 g_vl[QKVN];

// ---------------- PTX helpers (sm_80-era, safe on plain sm_100) ----------------
__device__ __forceinline__ uint32_t smem_u32(const void* p) {
    uint32_t a;
    asm("{ .reg .u64 t; cvta.to.shared.u64 t, %1; cvt.u32.u64 %0, t; }" : "=r"(a) : "l"(p));
    return a;
}
#define CP_ASYNC16(dst, src) \
    asm volatile("cp.async.cg.shared.global [%0], [%1], 16;" :: "r"(dst), "l"(src))
#define CP_COMMIT() asm volatile("cp.async.commit_group;" ::: "memory")
#define CP_WAIT0()  asm volatile("cp.async.wait_group 0;" ::: "memory")
#define CP_WAIT1()  asm volatile("cp.async.wait_group 1;" ::: "memory")

__device__ __forceinline__ void ldmx4(uint32_t* r, uint32_t addr) {
    asm volatile("ldmatrix.sync.aligned.m8n8.x4.shared.b16 {%0,%1,%2,%3}, [%4];"
                 : "=r"(r[0]), "=r"(r[1]), "=r"(r[2]), "=r"(r[3]) : "r"(addr));
}
__device__ __forceinline__ void ldmx4t(uint32_t* r, uint32_t addr) {
    asm volatile("ldmatrix.sync.aligned.m8n8.x4.trans.shared.b16 {%0,%1,%2,%3}, [%4];"
                 : "=r"(r[0]), "=r"(r[1]), "=r"(r[2]), "=r"(r[3]) : "r"(addr));
}
__device__ __forceinline__ void mma_bf16(float* d, const uint32_t* a, const uint32_t* b) {
    asm volatile(
        "mma.sync.aligned.m16n8k16.row.col.f32.bf16.bf16.f32 "
        "{%0,%1,%2,%3}, {%4,%5,%6,%7}, {%8,%9}, {%0,%1,%2,%3};"
        : "+f"(d[0]), "+f"(d[1]), "+f"(d[2]), "+f"(d[3])
        : "r"(a[0]), "r"(a[1]), "r"(a[2]), "r"(a[3]), "r"(b[0]), "r"(b[1]));
}
// pack fp32 pair (p0 -> low, p1 -> high) into bf16x2 hi part + residual lo part
__device__ __forceinline__ void pack_hilo(float p0, float p1, uint32_t& hp, uint32_t& lp) {
    asm("cvt.rn.bf16x2.f32 %0, %1, %2;" : "=r"(hp) : "f"(p1), "f"(p0));
    float h0 = __uint_as_float(hp << 16);
    float h1 = __uint_as_float(hp & 0xFFFF0000u);
    float l0 = p0 - h0, l1 = p1 - h1;
    asm("cvt.rn.bf16x2.f32 %0, %1, %2;" : "=r"(lp) : "f"(l1), "f"(l0));
}

// ---------------- fused fp32 -> bf16 hi/lo split for x, Wqkv, Wout ----------------
__global__ void split3_bf16(const float* __restrict__ x,
                            const float* __restrict__ wq,
                            const float* __restrict__ wo,
                            __nv_bfloat16* __restrict__ xhi, __nv_bfloat16* __restrict__ xlo,
                            __nv_bfloat16* __restrict__ wqh, __nv_bfloat16* __restrict__ wql,
                            __nv_bfloat16* __restrict__ woh, __nv_bfloat16* __restrict__ wol)
{
    const int n_x = MROWS * DD / 4;
    const int n_q = 3 * DD * DD / 4;
    const int n_o = DD * DD / 4;
    int i = blockIdx.x * 256 + threadIdx.x;
    const float* s; __nv_bfloat16 *hi, *lo;
    if (i < n_x) { s = x; hi = xhi; lo = xlo; }
    else if (i < n_x + n_q) { i -= n_x; s = wq; hi = wqh; lo = wql; }
    else {
        i -= n_x + n_q;
        if (i >= n_o) return;
        s = wo; hi = woh; lo = wol;
    }
    float4 v = ((const float4*)s)[i];
    __nv_bfloat16 h0 = __float2bfloat16(v.x), h1 = __float2bfloat16(v.y);
    __nv_bfloat16 h2 = __float2bfloat16(v.z), h3 = __float2bfloat16(v.w);
    __nv_bfloat16 l0 = __float2bfloat16(v.x - __bfloat162float(h0));
    __nv_bfloat16 l1 = __float2bfloat16(v.y - __bfloat162float(h1));
    __nv_bfloat16 l2 = __float2bfloat16(v.z - __bfloat162float(h2));
    __nv_bfloat16 l3 = __float2bfloat16(v.w - __bfloat162float(h3));
    __nv_bfloat162* hp = (__nv_bfloat162*)hi;
    __nv_bfloat162* lp = (__nv_bfloat162*)lo;
    hp[2 * i]     = __nv_bfloat162(h0, h1);
    hp[2 * i + 1] = __nv_bfloat162(h2, h3);
    lp[2 * i]     = __nv_bfloat162(l0, l1);
    lp[2 * i + 1] = __nv_bfloat162(l2, l3);
}

// ---------------- GEMM mainloop (shared by both kernels via macro) ----------------
#define GK 32
#define SROWB 80
#define TBYTES (128 * SROWB)
#define GEMM_SMEM (8 * TBYTES)         // 81920
#define STG 133                        // fp32 staging stride (fused epilogue)

#define GEMM_MAINLOOP(ACC)                                                            \
    const uint32_t sb = smem_u32(smg);                                                \
    const int tid = threadIdx.x;                                                      \
    const int wid = tid >> 5, lane = tid & 31;                                        \
    const int wm = wid >> 2, wn = wid & 3;                                            \
    const int brow = blockIdx.y * 128, bcol = blockIdx.x * 128;                       \
    const int nch = K / GK;                                                           \
    const __nv_bfloat16* srcs[4] = { Ah, Al, Bh, Bl };                                \
    auto load_chunk = [&](int c) {                                                    \
        const uint32_t base = sb + (uint32_t)(c & 1) * 4 * TBYTES;                    \
        const size_t ka = (size_t)c * GK;                                             \
        _Pragma("unroll")                                                             \
        for (int t = 0; t < 4; t++) {                                                 \
            const __nv_bfloat16* s = srcs[t];                                         \
            const int rowbase = (t < 2) ? brow : bcol;                                \
            _Pragma("unroll")                                                         \
            for (int j = 0; j < 2; j++) {                                             \
                int i = tid * 2 + j;                                                  \
                int r = i >> 2, ch = i & 3;                                           \
                const __nv_bfloat16* g = s + (size_t)(rowbase + r) * K + ka + ch * 8; \
                CP_ASYNC16(base + t * TBYTES + r * SROWB + ch * 16, g);               \
            }                                                                         \
        }                                                                             \
        CP_COMMIT();                                                                  \
    };                                                                                \
    _Pragma("unroll")                                                                 \
    for (int mt = 0; mt < 4; mt++)                                                    \
        _Pragma("unroll")                                                             \
        for (int nt = 0; nt < 4; nt++)                                                \
            _Pragma("unroll")                                                         \
            for (int e = 0; e < 4; e++) ACC[mt][nt][e] = 0.f;                         \
    const uint32_t a_row = (uint32_t)(wm * 64 + (lane & 15)) * SROWB + (lane >> 4) * 16; \
    const uint32_t b_row0 = (uint32_t)(wn * 32 + ((lane >> 4) & 1) * 8 + (lane & 7)) * SROWB \
                            + ((lane >> 3) & 1) * 16;                                 \
    load_chunk(0);                                                                    \
    for (int c = 0; c < nch; c++) {                                                   \
        if (c + 1 < nch) { load_chunk(c + 1); CP_WAIT1(); }                           \
        else CP_WAIT0();                                                              \
        __syncthreads();                                                              \
        const uint32_t bufb = sb + (uint32_t)(c & 1) * 4 * TBYTES;                    \
        _Pragma("unroll")                                                             \
        for (int ks = 0; ks < 2; ks++) {                                              \
            const uint32_t ko = ks * 32;                                              \
            uint32_t ah[4][4], al[4][4];                                              \
            _Pragma("unroll")                                                         \
            for (int mt = 0; mt < 4; mt++) {                                          \
                uint32_t addr = bufb + a_row + (uint32_t)(mt * 16) * SROWB + ko;      \
                ldmx4(ah[mt], addr);                                                  \
                ldmx4(al[mt], addr + TBYTES);                                         \
            }                                                                         \
            uint32_t bh[4][2], bl[4][2];                                              \
            _Pragma("unroll")                                                         \
            for (int p = 0; p < 2; p++) {                                             \
                uint32_t addr = bufb + 2 * TBYTES + b_row0 + (uint32_t)(p * 16) * SROWB + ko; \
                uint32_t rh[4], rl[4];                                                \
                ldmx4(rh, addr);                                                      \
                ldmx4(rl, addr + TBYTES);                                             \
                bh[2*p][0] = rh[0]; bh[2*p][1] = rh[1];                               \
                bh[2*p+1][0] = rh[2]; bh[2*p+1][1] = rh[3];                           \
                bl[2*p][0] = rl[0]; bl[2*p][1] = rl[1];                               \
                bl[2*p+1][0] = rl[2]; bl[2*p+1][1] = rl[3];                           \
            }                                                                         \
            _Pragma("unroll")                                                         \
            for (int mt = 0; mt < 4; mt++)                                            \
                _Pragma("unroll")                                                     \
                for (int nt = 0; nt < 4; nt++) {                                      \
                    mma_bf16(ACC[mt][nt], ah[mt], bh[nt]);                            \
                    mma_bf16(ACC[mt][nt], ah[mt], bl[nt]);                            \
                    mma_bf16(ACC[mt][nt], al[mt], bh[nt]);                            \
                }                                                                     \
        }                                                                             \
        __syncthreads();                                                              \
    }

// ---------------- plain GEMM (fp32 C epilogue) — exact R10 behavior ----------------
__global__ __launch_bounds__(256, 2) void gemm_bf16s(
    const __nv_bfloat16* __restrict__ Ah, const __nv_bfloat16* __restrict__ Al,
    const __nv_bfloat16* __restrict__ Bh, const __nv_bfloat16* __restrict__ Bl,
    float* __restrict__ C, int M, int N, int K)
{
    extern __shared__ char smg[];
    float acc[4][4][4];
    GEMM_MAINLOOP(acc)

    const int g = lane >> 2, t4 = lane & 3;
    #pragma unroll
    for (int mt = 0; mt < 4; mt++) {
        #pragma unroll
        for (int nt = 0; nt < 4; nt++) {
            int row = brow + wm * 64 + mt * 16 + g;
            int col = bcol + wn * 32 + nt * 8 + 2 * t4;
            float* p0 = C + (size_t)row * N + col;
            float* p1 = C + (size_t)(row + 8) * N + col;
            p0[0] = acc[mt][nt][0]; p0[1] = acc[mt][nt][1];
            p1[0] = acc[mt][nt][2]; p1[1] = acc[mt][nt][3];
        }
    }
}

// ---------------- QKV GEMM with fused RoPE + bf16 hi/lo epilogue (separate kernel) --
__global__ __launch_bounds__(256, 2) void gemm_qkv_rope(
    const __nv_bfloat16* __restrict__ Ah, const __nv_bfloat16* __restrict__ Al,
    const __nv_bfloat16* __restrict__ Bh, const __nv_bfloat16* __restrict__ Bl,
    int M, int N, int K,
    const float* __restrict__ cosT, const float* __restrict__ sinT)
{
    extern __shared__ char smg[];
    float acc[4][4][4];
    GEMM_MAINLOOP(acc)

    const int g = lane >> 2, t4 = lane & 3;

    // stage the 128x128 fp32 tile in smem (reuse tile buffers; safe after final sync)
    float* stage = (float*)smg;
    #pragma unroll
    for (int mt = 0; mt < 4; mt++) {
        #pragma unroll
        for (int nt = 0; nt < 4; nt++) {
            int r = wm * 64 + mt * 16 + g;
            int cc = wn * 32 + nt * 8 + 2 * t4;
            stage[r * STG + cc]           = acc[mt][nt][0];
            stage[r * STG + cc + 1]       = acc[mt][nt][1];
            stage[(r + 8) * STG + cc]     = acc[mt][nt][2];
            stage[(r + 8) * STG + cc + 1] = acc[mt][nt][3];
        }
    }
    __syncthreads();

    const int region = bcol >> 11;              // 0:q 1:k 2:v
    const int h = (bcol & 2047) >> 7;
    const int r = tid >> 1;
    const int cb = (tid & 1) * 32;
    const int grow = brow + r;
    const int b = grow >> 11;                   // / TT
    const int t = grow & (TT - 1);
    const size_t obase = (((size_t)(b * HH + h)) * TT + t) * HDD;

    __nv_bfloat16 *oh, *ol;
    if (region == 0)      { oh = g_qh; ol = g_ql; }
    else if (region == 1) { oh = g_kh; ol = g_kl; }
    else                  { oh = g_vh; ol = g_vl; }

    if (region == 2) {
        #pragma unroll
        for (int j = 0; j < 32; j += 2) {
            float u0 = stage[r * STG + cb + j],      u1 = stage[r * STG + cb + j + 1];
            float w0 = stage[r * STG + cb + 64 + j], w1 = stage[r * STG + cb + 65 + j];
            uint32_t hp, lp;
            pack_hilo(u0, u1, hp, lp);
            *(uint32_t*)&oh[obase + cb + j] = hp;      *(uint32_t*)&ol[obase + cb + j] = lp;
            pack_hilo(w0, w1, hp, lp);
            *(uint32_t*)&oh[obase + cb + 64 + j] = hp; *(uint32_t*)&ol[obase + cb + 64 + j] = lp;
        }
    } else {
        const float sc = (region == 0) ? 0.12751744509597396f : 1.f;  // 1/sqrt(128)*log2e
        #pragma unroll
        for (int j = 0; j < 32; j += 2) {
            int cc = cb + j;
            float u0 = stage[r * STG + cc],      u1 = stage[r * STG + cc + 1];
            float v0 = stage[r * STG + cc + 64], v1 = stage[r * STG + cc + 65];
            float cs0 = cosT[t * HDD + cc],      cs1 = cosT[t * HDD + cc + 1];
            float sn0 = sinT[t * HDD + cc],      sn1 = sinT[t * HDD + cc + 1];
            float cp0 = cosT[t * HDD + cc + 64], cp1 = cosT[t * HDD + cc + 65];
            float sp0 = sinT[t * HDD + cc + 64], sp1 = sinT[t * HDD + cc + 65];
            float o0 = fmaf(u0, cs0, -v0 * sn0) * sc;
            float o1 = fmaf(u1, cs1, -v1 * sn1) * sc;
            float p0 = fmaf(v0, cp0,  u0 * sp0) * sc;
            float p1 = fmaf(v1, cp1,  u1 * sp1) * sc;
            uint32_t hp, lp;
            pack_hilo(o0, o1, hp, lp);
            *(uint32_t*)&oh[obase + cc] = hp;      *(uint32_t*)&ol[obase + cc] = lp;
            pack_hilo(p0, p1, hp, lp);
            *(uint32_t*)&oh[obase + cc + 64] = hp; *(uint32_t*)&ol[obase + cc + 64] = lp;
        }
    }
}

// ---------------- tensor-core flash attention (unchanged from R10) ----------------
#define FQ2 128
#define FK2 64
#define FSTR 272
#define SM_QH 0
#define SM_QL (FQ2*FSTR)
#define SM_K  (2*FQ2*FSTR)
#define SM_V  (SM_K + 2*2*FK2*FSTR)
#define KVBUF (2*FK2*FSTR)
#define HLOFF (FK2*FSTR)
#define FLASH2_SMEM (SM_V + 2*KVBUF)    // 208896

__global__ __launch_bounds__(256, 1) void flash_mma()
{
    extern __shared__ char smf[];
    const uint32_t sb = smem_u32(smf);
    const int tid = threadIdx.x;
    const int wid = tid >> 5, lane = tid & 31;

    const int l = blockIdx.x + 16 * blockIdx.y + 256 * blockIdx.z;   // 0..511
    const int qt = (TT / FQ2 - 1) - (l >> 5);                        // 15..0
    const int bh = l & 31;
    const int h = bh & 15, b = bh >> 4;

    const size_t hb = ((size_t)(b * HH + h)) * TT * HDD;
    const size_t qb = hb + (size_t)qt * FQ2 * HDD;

    auto load_kv = [&](int kt) {
        const uint32_t kbase = sb + SM_K + (uint32_t)(kt & 1) * KVBUF;
        const uint32_t vbase = sb + SM_V + (uint32_t)(kt & 1) * KVBUF;
        const size_t kb = hb + (size_t)kt * FK2 * HDD;
        #pragma unroll
        for (int j = 0; j < 4; j++) {
            int i = tid + j * 256;
            int r = i >> 4, ch = i & 15;
            size_t goff = kb + (size_t)r * HDD + ch * 8;
            uint32_t soff = (uint32_t)r * FSTR + ch * 16;
            CP_ASYNC16(kbase + soff, g_kh + goff);
            CP_ASYNC16(kbase + HLOFF + soff, g_kl + goff);
            CP_ASYNC16(vbase + soff, g_vh + goff);
            CP_ASYNC16(vbase + HLOFF + soff, g_vl + goff);
        }
        CP_COMMIT();
    };

    #pragma unroll
    for (int j = 0; j < 8; j++) {
        int i = tid + j * 256;
        int r = i >> 4, ch = i & 15;
        size_t goff = qb + (size_t)r * HDD + ch * 8;
        uint32_t soff = (uint32_t)r * FSTR + ch * 16;
        CP_ASYNC16(sb + SM_QH + soff, g_qh + goff);
        CP_ASYNC16(sb + SM_QL + soff, g_ql + goff);
    }
    CP_COMMIT();
    load_kv(0);

    const uint32_t aq  = sb + SM_QH + (uint32_t)(wid * 16 + (lane & 15)) * FSTR + (lane >> 4) * 16;
    const uint32_t akr = (uint32_t)((lane & 7) + ((lane >> 4) << 3)) * FSTR + ((lane >> 3) & 1) * 16;
    const uint32_t avr = (uint32_t)((lane & 7) + ((lane >> 3) & 1) * 8) * FSTR + ((lane >> 4) << 3) * 2;

    CP_WAIT1();
    __syncthreads();
    uint32_t qhf[8][4];
    #pragma unroll
    for (int ks = 0; ks < 8; ks++)
        ldmx4(qhf[ks], aq + ks * 32);

    float oacc[16][4];
    #pragma unroll
    for (int i = 0; i < 16; i++)
        #pragma unroll
        for (int e = 0; e < 4; e++) oacc[i][e] = 0.f;
    float mrow[2] = { -1e30f, -1e30f }, lrow[2] = { 0.f, 0.f };

    const int ktmax = 2 * qt + 1;
    for (int kt = 0; kt <= ktmax; kt++) {
        if (kt < ktmax) { load_kv(kt + 1); CP_WAIT1(); }
        else CP_WAIT0();
        __syncthreads();

        const uint32_t kbase = sb + SM_K + (uint32_t)(kt & 1) * KVBUF;
        const uint32_t vbase = sb + SM_V + (uint32_t)(kt & 1) * KVBUF;

        float sacc[8][4];
        #pragma unroll
        for (int nt = 0; nt < 8; nt++)
            #pragma unroll
            for (int e = 0; e < 4; e++) sacc[nt][e] = 0.f;

        #pragma unroll
        for (int ks = 0; ks < 8; ks++) {
            uint32_t ql4[4];
            ldmx4(ql4, aq + (SM_QL - SM_QH) + ks * 32);
            #pragma unroll
            for (int p = 0; p < 4; p++) {
                uint32_t kh4[4], kl4[4];
                uint32_t kaddr = kbase + akr + (uint32_t)(p * 16) * FSTR + ks * 32;
                ldmx4(kh4, kaddr);
                ldmx4(kl4, kaddr + HLOFF);
                mma_bf16(sacc[2*p],   qhf[ks], &kh4[0]);
                mma_bf16(sacc[2*p],   qhf[ks], &kl4[0]);
                mma_bf16(sacc[2*p],   ql4,     &kh4[0]);
                mma_bf16(sacc[2*p+1], qhf[ks], &kh4[2]);
                mma_bf16(sacc[2*p+1], qhf[ks], &kl4[2]);
                mma_bf16(sacc[2*p+1], ql4,     &kh4[2]);
            }
        }

        if (kt >= 2 * qt) {
            const int qrow0 = qt * FQ2 + wid * 16 + (lane >> 2);
            #pragma unroll
            for (int nt = 0; nt < 8; nt++) {
                int kc = kt * FK2 + nt * 8 + 2 * (lane & 3);
                if (kc     > qrow0)     sacc[nt][0] = -1e30f;
                if (kc + 1 > qrow0)     sacc[nt][1] = -1e30f;
                if (kc     > qrow0 + 8) sacc[nt][2] = -1e30f;
                if (kc + 1 > qrow0 + 8) sacc[nt][3] = -1e30f;
            }
        }

        #pragma unroll
        for (int r = 0; r < 2; r++) {
            float mt = -1e30f;
            #pragma unroll
            for (int nt = 0; nt < 8; nt++)
                mt = fmaxf(mt, fmaxf(sacc[nt][2 * r], sacc[nt][2 * r + 1]));
            mt = fmaxf(mt, __shfl_xor_sync(0xffffffffu, mt, 1));
            mt = fmaxf(mt, __shfl_xor_sync(0xffffffffu, mt, 2));
            float mnew = fmaxf(mrow[r], mt);
            float alpha = exp2f(mrow[r] - mnew);
            mrow[r] = mnew;
            float rs = 0.f;
            #pragma unroll
            for (int nt = 0; nt < 8; nt++) {
                float p0 = exp2f(sacc[nt][2 * r]     - mnew);
                float p1 = exp2f(sacc[nt][2 * r + 1] - mnew);
                sacc[nt][2 * r] = p0; sacc[nt][2 * r + 1] = p1;
                rs += p0 + p1;
            }
            rs += __shfl_xor_sync(0xffffffffu, rs, 1);
            rs += __shfl_xor_sync(0xffffffffu, rs, 2);
            lrow[r] = lrow[r] * alpha + rs;
            #pragma unroll
            for (int nt2 = 0; nt2 < 16; nt2++) {
                oacc[nt2][2 * r]     *= alpha;
                oacc[nt2][2 * r + 1] *= alpha;
            }
        }

        uint32_t ph[4][4], pl[4][4];
        #pragma unroll
        for (int ks2 = 0; ks2 < 4; ks2++) {
            pack_hilo(sacc[2*ks2][0],   sacc[2*ks2][1],   ph[ks2][0], pl[ks2][0]);
            pack_hilo(sacc[2*ks2][2],   sacc[2*ks2][3],   ph[ks2][1], pl[ks2][1]);
            pack_hilo(sacc[2*ks2+1][0], sacc[2*ks2+1][1], ph[ks2][2], pl[ks2][2]);
            pack_hilo(sacc[2*ks2+1][2], sacc[2*ks2+1][3], ph[ks2][3], pl[ks2][3]);
        }

        #pragma unroll
        for (int ks2 = 0; ks2 < 4; ks2++) {
            #pragma unroll
            for (int np = 0; np < 8; np++) {
                uint32_t vh4[4], vl4[4];
                uint32_t vaddr = vbase + avr + (uint32_t)(ks2 * 16) * FSTR + (np * 16) * 2;
                ldmx4t(vh4, vaddr);
                ldmx4t(vl4, vaddr + HLOFF);
                mma_bf16(oacc[2*np],   ph[ks2], &vh4[0]);
                mma_bf16(oacc[2*np],   ph[ks2], &vl4[0]);
                mma_bf16(oacc[2*np],   pl[ks2], &vh4[0]);
                mma_bf16(oacc[2*np+1], ph[ks2], &vh4[2]);
                mma_bf16(oacc[2*np+1], ph[ks2], &vl4[2]);
                mma_bf16(oacc[2*np+1], pl[ks2], &vh4[2]);
            }
        }
        __syncthreads();
    }

    const float inv0 = 1.f / lrow[0], inv1 = 1.f / lrow[1];
    const int row0 = qt * FQ2 + wid * 16 + (lane >> 2);
    #pragma unroll
    for (int nt2 = 0; nt2 < 16; nt2++) {
        int col = h * HDD + nt2 * 8 + 2 * (lane & 3);
        size_t i0 = (size_t)(b * TT + row0) * DD + col;
        size_t i1 = (size_t)(b * TT + row0 + 8) * DD + col;
        uint32_t hp, lp;
        pack_hilo(oacc[nt2][0] * inv0, oacc[nt2][1] * inv0, hp, lp);
        *(uint32_t*)&g_ahi[i0] = hp; *(uint32_t*)&g_alo[i0] = lp;
        pack_hilo(oacc[nt2][2] * inv1, oacc[nt2][3] * inv1, hp, lp);
        *(uint32_t*)&g_ahi[i1] = hp; *(uint32_t*)&g_alo[i1] = lp;
    }
}

// ---------------- launch ----------------
extern "C" void kernel_launch(void* const* d_in, const int* in_sizes, int n_in,
                              void* d_out, int out_size)
{
    const float* x    = (const float*)d_in[0];
    const float* cosT = (const float*)d_in[1];
    const float* sinT = (const float*)d_in[2];
    const float* Wqkv = (const float*)d_in[3];
    const float* Wout = (const float*)d_in[4];
    float* out = (float*)d_out;

    __nv_bfloat16 *xhi, *xlo, *wqh, *wql, *woh, *wol, *ahi, *alo;
    cudaGetSymbolAddress((void**)&xhi, g_xhi);
    cudaGetSymbolAddress((void**)&xlo, g_xlo);
    cudaGetSymbolAddress((void**)&wqh, g_wqh);
    cudaGetSymbolAddress((void**)&wql, g_wql);
    cudaGetSymbolAddress((void**)&woh, g_woh);
    cudaGetSymbolAddress((void**)&wol, g_wol);
    cudaGetSymbolAddress((void**)&ahi, g_ahi);
    cudaGetSymbolAddress((void**)&alo, g_alo);

    cudaFuncSetAttribute(gemm_bf16s, cudaFuncAttributeMaxDynamicSharedMemorySize, GEMM_SMEM);
    cudaFuncSetAttribute(gemm_qkv_rope, cudaFuncAttributeMaxDynamicSharedMemorySize, GEMM_SMEM);
    cudaFuncSetAttribute(flash_mma, cudaFuncAttributeMaxDynamicSharedMemorySize, FLASH2_SMEM);

    // 0) fused bf16 hi/lo splits of x, Wqkv, Wout
    {
        int total = MROWS * DD / 4 + 3 * DD * DD / 4 + DD * DD / 4;
        split3_bf16<<<(total + 255) / 256, 256>>>(x, Wqkv, Wout,
                                                  xhi, xlo, wqh, wql, woh, wol);
    }

    // 1) QKV projection with fused RoPE + hi/lo epilogue (separate kernel)
    gemm_qkv_rope<<<dim3(3 * DD / 128, MROWS / 128), 256, GEMM_SMEM>>>(
        xhi, xlo, wqh, wql, MROWS, 3 * DD, DD, cosT, sinT);

    // 2) causal flash attention (tensor cores), writes g_ahi/g_alo
    flash_mma<<<dim3(TT / FQ2, HH, BB), 256, FLASH2_SMEM>>>();

    // 3) output projection (pristine R10 kernel)
    gemm_bf16s<<<dim3(DD / 128, MROWS / 128), 256, GEMM_SMEM>>>(
        ahi, alo, woh, wol, out, MROWS, DD, DD);
}

// round 15
// speedup vs baseline: 1.0871x; 1.0871x over previous
#include <cuda_runtime.h>
#include <cuda_bf16.h>
#include <cstdint>
#include <cstddef>

#define BB 2
#define TT 2048
#define DD 2048
#define HH 16
#define HDD 128
#define MROWS (BB*TT)   // 4096

// ---------------- scratch (static device globals; no runtime alloc) ----------------
__device__ float g_qkv[(size_t)BB * TT * 3 * DD];   // [B,T,3D]

// bf16 hi/lo splits
__device__ __nv_bfloat16 g_xhi[(size_t)MROWS * DD];
__device__ __nv_bfloat16 g_xlo[(size_t)MROWS * DD];
__device__ __nv_bfloat16 g_wqh[(size_t)3 * DD * DD];
__device__ __nv_bfloat16 g_wql[(size_t)3 * DD * DD];
__device__ __nv_bfloat16 g_woh[(size_t)DD * DD];
__device__ __nv_bfloat16 g_wol[(size_t)DD * DD];
__device__ __nv_bfloat16 g_ahi[(size_t)MROWS * DD];   // attn out (written by flash)
__device__ __nv_bfloat16 g_alo[(size_t)MROWS * DD];

// q/k/v hi-lo bf16, [B,H,T,HD]
#define QKVN ((size_t)BB * HH * TT * HDD)
__device__ __nv_bfloat16 g_qh[QKVN];
__device__ __nv_bfloat16 g_ql[QKVN];
__device__ __nv_bfloat16 g_kh[QKVN];
__device__ __nv_bfloat16 g_kl[QKVN];
__device__ __nv_bfloat16 g_vh[QKVN];
__device__ __nv_bfloat16 g_vl[QKVN];

// ---------------- PTX helpers (sm_80-era, safe on plain sm_100) ----------------
__device__ __forceinline__ uint32_t smem_u32(const void* p) {
    uint32_t a;
    asm("{ .reg .u64 t; cvta.to.shared.u64 t, %1; cvt.u32.u64 %0, t; }" : "=r"(a) : "l"(p));
    return a;
}
#define CP_ASYNC16(dst, src) \
    asm volatile("cp.async.cg.shared.global [%0], [%1], 16;" :: "r"(dst), "l"(src))
#define CP_COMMIT() asm volatile("cp.async.commit_group;" ::: "memory")
#define CP_WAIT0()  asm volatile("cp.async.wait_group 0;" ::: "memory")
#define CP_WAIT1()  asm volatile("cp.async.wait_group 1;" ::: "memory")

__device__ __forceinline__ void ldmx4(uint32_t* r, uint32_t addr) {
    asm volatile("ldmatrix.sync.aligned.m8n8.x4.shared.b16 {%0,%1,%2,%3}, [%4];"
                 : "=r"(r[0]), "=r"(r[1]), "=r"(r[2]), "=r"(r[3]) : "r"(addr));
}
__device__ __forceinline__ void ldmx4t(uint32_t* r, uint32_t addr) {
    asm volatile("ldmatrix.sync.aligned.m8n8.x4.trans.shared.b16 {%0,%1,%2,%3}, [%4];"
                 : "=r"(r[0]), "=r"(r[1]), "=r"(r[2]), "=r"(r[3]) : "r"(addr));
}
__device__ __forceinline__ void mma_bf16(float* d, const uint32_t* a, const uint32_t* b) {
    asm volatile(
        "mma.sync.aligned.m16n8k16.row.col.f32.bf16.bf16.f32 "
        "{%0,%1,%2,%3}, {%4,%5,%6,%7}, {%8,%9}, {%0,%1,%2,%3};"
        : "+f"(d[0]), "+f"(d[1]), "+f"(d[2]), "+f"(d[3])
        : "r"(a[0]), "r"(a[1]), "r"(a[2]), "r"(a[3]), "r"(b[0]), "r"(b[1]));
}
// pack fp32 pair (p0 -> low, p1 -> high) into bf16x2 hi part + residual lo part
__device__ __forceinline__ void pack_hilo(float p0, float p1, uint32_t& hp, uint32_t& lp) {
    asm("cvt.rn.bf16x2.f32 %0, %1, %2;" : "=r"(hp) : "f"(p1), "f"(p0));
    float h0 = __uint_as_float(hp << 16);
    float h1 = __uint_as_float(hp & 0xFFFF0000u);
    float l0 = p0 - h0, l1 = p1 - h1;
    asm("cvt.rn.bf16x2.f32 %0, %1, %2;" : "=r"(lp) : "f"(l1), "f"(l0));
}

// ---------------- fused fp32 -> bf16 hi/lo split for x, Wqkv, Wout ----------------
__global__ void split3_bf16(const float* __restrict__ x,
                            const float* __restrict__ wq,
                            const float* __restrict__ wo,
                            __nv_bfloat16* __restrict__ xhi, __nv_bfloat16* __restrict__ xlo,
                            __nv_bfloat16* __restrict__ wqh, __nv_bfloat16* __restrict__ wql,
                            __nv_bfloat16* __restrict__ woh, __nv_bfloat16* __restrict__ wol)
{
    const int n_x = MROWS * DD / 4;
    const int n_q = 3 * DD * DD / 4;
    const int n_o = DD * DD / 4;
    int i = blockIdx.x * 256 + threadIdx.x;
    const float* s; __nv_bfloat16 *hi, *lo;
    if (i < n_x) { s = x; hi = xhi; lo = xlo; }
    else if (i < n_x + n_q) { i -= n_x; s = wq; hi = wqh; lo = wql; }
    else {
        i -= n_x + n_q;
        if (i >= n_o) return;
        s = wo; hi = woh; lo = wol;
    }
    float4 v = ((const float4*)s)[i];
    __nv_bfloat16 h0 = __float2bfloat16(v.x), h1 = __float2bfloat16(v.y);
    __nv_bfloat16 h2 = __float2bfloat16(v.z), h3 = __float2bfloat16(v.w);
    __nv_bfloat16 l0 = __float2bfloat16(v.x - __bfloat162float(h0));
    __nv_bfloat16 l1 = __float2bfloat16(v.y - __bfloat162float(h1));
    __nv_bfloat16 l2 = __float2bfloat16(v.z - __bfloat162float(h2));
    __nv_bfloat16 l3 = __float2bfloat16(v.w - __bfloat162float(h3));
    __nv_bfloat162* hp = (__nv_bfloat162*)hi;
    __nv_bfloat162* lp = (__nv_bfloat162*)lo;
    hp[2 * i]     = __nv_bfloat162(h0, h1);
    hp[2 * i + 1] = __nv_bfloat162(h2, h3);
    lp[2 * i]     = __nv_bfloat162(l0, l1);
    lp[2 * i + 1] = __nv_bfloat162(l2, l3);
}

// ---------------- mma.sync bf16-split GEMM: C[M,N] = A[M,K] @ B[N,K]^T ----------------
// Term loop hoisted outermost: 16 independent accumulators between dependent MMAs.
#define GK 32
#define SROWB 80
#define TBYTES (128 * SROWB)
#define GEMM_SMEM (8 * TBYTES)         // 81920

__global__ __launch_bounds__(256, 2) void gemm_bf16s(
    const __nv_bfloat16* __restrict__ Ah, const __nv_bfloat16* __restrict__ Al,
    const __nv_bfloat16* __restrict__ Bh, const __nv_bfloat16* __restrict__ Bl,
    float* __restrict__ C, int M, int N, int K)
{
    extern __shared__ char smg[];
    const uint32_t sb = smem_u32(smg);
    const int tid = threadIdx.x;
    const int wid = tid >> 5, lane = tid & 31;
    const int wm = wid >> 2, wn = wid & 3;
    const int brow = blockIdx.y * 128, bcol = blockIdx.x * 128;
    const int nch = K / GK;

    const __nv_bfloat16* srcs[4] = { Ah, Al, Bh, Bl };

    auto load_chunk = [&](int c) {
        const uint32_t base = sb + (uint32_t)(c & 1) * 4 * TBYTES;
        const size_t ka = (size_t)c * GK;
        #pragma unroll
        for (int t = 0; t < 4; t++) {
            const __nv_bfloat16* s = srcs[t];
            const int rowbase = (t < 2) ? brow : bcol;
            #pragma unroll
            for (int j = 0; j < 2; j++) {
                int i = tid * 2 + j;
                int r = i >> 2, ch = i & 3;
                const __nv_bfloat16* g = s + (size_t)(rowbase + r) * K + ka + ch * 8;
                CP_ASYNC16(base + t * TBYTES + r * SROWB + ch * 16, g);
            }
        }
        CP_COMMIT();
    };

    float acc[4][4][4];
    #pragma unroll
    for (int mt = 0; mt < 4; mt++)
        #pragma unroll
        for (int nt = 0; nt < 4; nt++)
            #pragma unroll
            for (int e = 0; e < 4; e++) acc[mt][nt][e] = 0.f;

    const uint32_t a_row = (uint32_t)(wm * 64 + (lane & 15)) * SROWB + (lane >> 4) * 16;
    const uint32_t b_row0 = (uint32_t)(wn * 32 + ((lane >> 4) & 1) * 8 + (lane & 7)) * SROWB
                            + ((lane >> 3) & 1) * 16;

    load_chunk(0);

    for (int c = 0; c < nch; c++) {
        if (c + 1 < nch) { load_chunk(c + 1); CP_WAIT1(); }
        else CP_WAIT0();
        __syncthreads();

        const uint32_t bufb = sb + (uint32_t)(c & 1) * 4 * TBYTES;
        #pragma unroll
        for (int ks = 0; ks < 2; ks++) {
            const uint32_t ko = ks * 32;
            uint32_t ah[4][4], al[4][4];
            #pragma unroll
            for (int mt = 0; mt < 4; mt++) {
                uint32_t addr = bufb + a_row + (uint32_t)(mt * 16) * SROWB + ko;
                ldmx4(ah[mt], addr);
                ldmx4(al[mt], addr + TBYTES);
            }
            uint32_t bh[4][2], bl[4][2];
            #pragma unroll
            for (int p = 0; p < 2; p++) {
                uint32_t addr = bufb + 2 * TBYTES + b_row0 + (uint32_t)(p * 16) * SROWB + ko;
                uint32_t rh[4], rl[4];
                ldmx4(rh, addr);
                ldmx4(rl, addr + TBYTES);
                bh[2*p][0] = rh[0]; bh[2*p][1] = rh[1];
                bh[2*p+1][0] = rh[2]; bh[2*p+1][1] = rh[3];
                bl[2*p][0] = rl[0]; bl[2*p][1] = rl[1];
                bl[2*p+1][0] = rl[2]; bl[2*p+1][1] = rl[3];
            }
            // term-major: per-acc order stays hh -> hl -> lh (bit-identical result),
            // but consecutive MMAs now hit 16 different accumulators (no RAW chains).
            #pragma unroll
            for (int mt = 0; mt < 4; mt++)
                #pragma unroll
                for (int nt = 0; nt < 4; nt++)
                    mma_bf16(acc[mt][nt], ah[mt], bh[nt]);
            #pragma unroll
            for (int mt = 0; mt < 4; mt++)
                #pragma unroll
                for (int nt = 0; nt < 4; nt++)
                    mma_bf16(acc[mt][nt], ah[mt], bl[nt]);
            #pragma unroll
            for (int mt = 0; mt < 4; mt++)
                #pragma unroll
                for (int nt = 0; nt < 4; nt++)
                    mma_bf16(acc[mt][nt], al[mt], bh[nt]);
        }
        __syncthreads();
    }

    const int g = lane >> 2, t4 = lane & 3;
    #pragma unroll
    for (int mt = 0; mt < 4; mt++) {
        #pragma unroll
        for (int nt = 0; nt < 4; nt++) {
            int row = brow + wm * 64 + mt * 16 + g;
            int col = bcol + wn * 32 + nt * 8 + 2 * t4;
            float* p0 = C + (size_t)row * N + col;
            float* p1 = C + (size_t)(row + 8) * N + col;
            p0[0] = acc[mt][nt][0]; p0[1] = acc[mt][nt][1];
            p1[0] = acc[mt][nt][2]; p1[1] = acc[mt][nt][3];
        }
    }
}

// ---------------- RoPE + split into bf16 hi/lo [B,H,T,HD]; q pre-scaled ----------------
// q scale = (1/sqrt(128)) * log2(e)  -> softmax runs in base 2
__global__ void rope_split(const float* __restrict__ qkv,
                           const float* __restrict__ cosT,
                           const float* __restrict__ sinT)
{
    const int idx = blockIdx.x;
    const int h = idx % HH;
    const int t = (idx / HH) % TT;
    const int b = idx / (HH * TT);
    const int c = threadIdx.x;

    const size_t ibase = ((size_t)(b * TT + t)) * (3 * DD) + h * HDD;
    float qv = qkv[ibase + c];
    float kv = qkv[ibase + DD + c];
    float vv = qkv[ibase + 2 * DD + c];
    float qp = qkv[ibase + (c ^ 64)];
    float kp = qkv[ibase + DD + (c ^ 64)];
    float cs = cosT[t * HDD + c];
    float sn = sinT[t * HDD + c];
    float sgn = (c < 64) ? -1.f : 1.f;

    float q = fmaf(qv, cs, sgn * qp * sn) * 0.12751744509597396f;  // 1/sqrt(128) * log2(e)
    float k = fmaf(kv, cs, sgn * kp * sn);

    const size_t o = (((size_t)(b * HH + h)) * TT + t) * HDD + c;
    __nv_bfloat16 qh = __float2bfloat16(q);
    __nv_bfloat16 kh = __float2bfloat16(k);
    __nv_bfloat16 vh = __float2bfloat16(vv);
    g_qh[o] = qh; g_ql[o] = __float2bfloat16(q - __bfloat162float(qh));
    g_kh[o] = kh; g_kl[o] = __float2bfloat16(k - __bfloat162float(kh));
    g_vh[o] = vh; g_vl[o] = __float2bfloat16(vv - __bfloat162float(vh));
}

// ---------------- tensor-core flash attention (R10 structure, unchanged) ----------
#define FQ2 128
#define FK2 64
#define FSTR 272
#define SM_QH 0
#define SM_QL (FQ2*FSTR)
#define SM_K  (2*FQ2*FSTR)
#define SM_V  (SM_K + 2*2*FK2*FSTR)
#define KVBUF (2*FK2*FSTR)
#define HLOFF (FK2*FSTR)
#define FLASH2_SMEM (SM_V + 2*KVBUF)    // 208896

__global__ __launch_bounds__(256, 1) void flash_mma()
{
    extern __shared__ char smf[];
    const uint32_t sb = smem_u32(smf);
    const int tid = threadIdx.x;
    const int wid = tid >> 5, lane = tid & 31;

    const int l = blockIdx.x + 16 * blockIdx.y + 256 * blockIdx.z;   // 0..511
    const int qt = (TT / FQ2 - 1) - (l >> 5);                        // 15..0
    const int bh = l & 31;
    const int h = bh & 15, b = bh >> 4;

    const size_t hb = ((size_t)(b * HH + h)) * TT * HDD;
    const size_t qb = hb + (size_t)qt * FQ2 * HDD;

    auto load_kv = [&](int kt) {
        const uint32_t kbase = sb + SM_K + (uint32_t)(kt & 1) * KVBUF;
        const uint32_t vbase = sb + SM_V + (uint32_t)(kt & 1) * KVBUF;
        const size_t kb = hb + (size_t)kt * FK2 * HDD;
        #pragma unroll
        for (int j = 0; j < 4; j++) {
            int i = tid + j * 256;
            int r = i >> 4, ch = i & 15;
            size_t goff = kb + (size_t)r * HDD + ch * 8;
            uint32_t soff = (uint32_t)r * FSTR + ch * 16;
            CP_ASYNC16(kbase + soff, g_kh + goff);
            CP_ASYNC16(kbase + HLOFF + soff, g_kl + goff);
            CP_ASYNC16(vbase + soff, g_vh + goff);
            CP_ASYNC16(vbase + HLOFF + soff, g_vl + goff);
        }
        CP_COMMIT();
    };

    #pragma unroll
    for (int j = 0; j < 8; j++) {
        int i = tid + j * 256;
        int r = i >> 4, ch = i & 15;
        size_t goff = qb + (size_t)r * HDD + ch * 8;
        uint32_t soff = (uint32_t)r * FSTR + ch * 16;
        CP_ASYNC16(sb + SM_QH + soff, g_qh + goff);
        CP_ASYNC16(sb + SM_QL + soff, g_ql + goff);
    }
    CP_COMMIT();
    load_kv(0);

    const uint32_t aq  = sb + SM_QH + (uint32_t)(wid * 16 + (lane & 15)) * FSTR + (lane >> 4) * 16;
    const uint32_t akr = (uint32_t)((lane & 7) + ((lane >> 4) << 3)) * FSTR + ((lane >> 3) & 1) * 16;
    const uint32_t avr = (uint32_t)((lane & 7) + ((lane >> 3) & 1) * 8) * FSTR + ((lane >> 4) << 3) * 2;

    CP_WAIT1();
    __syncthreads();
    uint32_t qhf[8][4];
    #pragma unroll
    for (int ks = 0; ks < 8; ks++)
        ldmx4(qhf[ks], aq + ks * 32);

    float oacc[16][4];
    #pragma unroll
    for (int i = 0; i < 16; i++)
        #pragma unroll
        for (int e = 0; e < 4; e++) oacc[i][e] = 0.f;
    float mrow[2] = { -1e30f, -1e30f }, lrow[2] = { 0.f, 0.f };

    const int ktmax = 2 * qt + 1;
    for (int kt = 0; kt <= ktmax; kt++) {
        if (kt < ktmax) { load_kv(kt + 1); CP_WAIT1(); }
        else CP_WAIT0();
        __syncthreads();

        const uint32_t kbase = sb + SM_K + (uint32_t)(kt & 1) * KVBUF;
        const uint32_t vbase = sb + SM_V + (uint32_t)(kt & 1) * KVBUF;

        float sacc[8][4];
        #pragma unroll
        for (int nt = 0; nt < 8; nt++)
            #pragma unroll
            for (int e = 0; e < 4; e++) sacc[nt][e] = 0.f;

        #pragma unroll
        for (int ks = 0; ks < 8; ks++) {
            uint32_t ql4[4];
            ldmx4(ql4, aq + (SM_QL - SM_QH) + ks * 32);
            #pragma unroll
            for (int p = 0; p < 4; p++) {
                uint32_t kh4[4], kl4[4];
                uint32_t kaddr = kbase + akr + (uint32_t)(p * 16) * FSTR + ks * 32;
                ldmx4(kh4, kaddr);
                ldmx4(kl4, kaddr + HLOFF);
                mma_bf16(sacc[2*p],   qhf[ks], &kh4[0]);
                mma_bf16(sacc[2*p],   qhf[ks], &kl4[0]);
                mma_bf16(sacc[2*p],   ql4,     &kh4[0]);
                mma_bf16(sacc[2*p+1], qhf[ks], &kh4[2]);
                mma_bf16(sacc[2*p+1], qhf[ks], &kl4[2]);
                mma_bf16(sacc[2*p+1], ql4,     &kh4[2]);
            }
        }

        if (kt >= 2 * qt) {
            const int qrow0 = qt * FQ2 + wid * 16 + (lane >> 2);
            #pragma unroll
            for (int nt = 0; nt < 8; nt++) {
                int kc = kt * FK2 + nt * 8 + 2 * (lane & 3);
                if (kc     > qrow0)     sacc[nt][0] = -1e30f;
                if (kc + 1 > qrow0)     sacc[nt][1] = -1e30f;
                if (kc     > qrow0 + 8) sacc[nt][2] = -1e30f;
                if (kc + 1 > qrow0 + 8) sacc[nt][3] = -1e30f;
            }
        }

        #pragma unroll
        for (int r = 0; r < 2; r++) {
            float mt = -1e30f;
            #pragma unroll
            for (int nt = 0; nt < 8; nt++)
                mt = fmaxf(mt, fmaxf(sacc[nt][2 * r], sacc[nt][2 * r + 1]));
            mt = fmaxf(mt, __shfl_xor_sync(0xffffffffu, mt, 1));
            mt = fmaxf(mt, __shfl_xor_sync(0xffffffffu, mt, 2));
            float mnew = fmaxf(mrow[r], mt);
            float alpha = exp2f(mrow[r] - mnew);
            mrow[r] = mnew;
            float rs = 0.f;
            #pragma unroll
            for (int nt = 0; nt < 8; nt++) {
                float p0 = exp2f(sacc[nt][2 * r]     - mnew);
                float p1 = exp2f(sacc[nt][2 * r + 1] - mnew);
                sacc[nt][2 * r] = p0; sacc[nt][2 * r + 1] = p1;
                rs += p0 + p1;
            }
            rs += __shfl_xor_sync(0xffffffffu, rs, 1);
            rs += __shfl_xor_sync(0xffffffffu, rs, 2);
            lrow[r] = lrow[r] * alpha + rs;
            #pragma unroll
            for (int nt2 = 0; nt2 < 16; nt2++) {
                oacc[nt2][2 * r]     *= alpha;
                oacc[nt2][2 * r + 1] *= alpha;
            }
        }

        uint32_t ph[4][4], pl[4][4];
        #pragma unroll
        for (int ks2 = 0; ks2 < 4; ks2++) {
            pack_hilo(sacc[2*ks2][0],   sacc[2*ks2][1],   ph[ks2][0], pl[ks2][0]);
            pack_hilo(sacc[2*ks2][2],   sacc[2*ks2][3],   ph[ks2][1], pl[ks2][1]);
            pack_hilo(sacc[2*ks2+1][0], sacc[2*ks2+1][1], ph[ks2][2], pl[ks2][2]);
            pack_hilo(sacc[2*ks2+1][2], sacc[2*ks2+1][3], ph[ks2][3], pl[ks2][3]);
        }

        #pragma unroll
        for (int ks2 = 0; ks2 < 4; ks2++) {
            #pragma unroll
            for (int np = 0; np < 8; np++) {
                uint32_t vh4[4], vl4[4];
                uint32_t vaddr = vbase + avr + (uint32_t)(ks2 * 16) * FSTR + (np * 16) * 2;
                ldmx4t(vh4, vaddr);
                ldmx4t(vl4, vaddr + HLOFF);
                mma_bf16(oacc[2*np],   ph[ks2], &vh4[0]);
                mma_bf16(oacc[2*np],   ph[ks2], &vl4[0]);
                mma_bf16(oacc[2*np],   pl[ks2], &vh4[0]);
                mma_bf16(oacc[2*np+1], ph[ks2], &vh4[2]);
                mma_bf16(oacc[2*np+1], ph[ks2], &vl4[2]);
                mma_bf16(oacc[2*np+1], pl[ks2], &vh4[2]);
            }
        }
        __syncthreads();
    }

    const float inv0 = 1.f / lrow[0], inv1 = 1.f / lrow[1];
    const int row0 = qt * FQ2 + wid * 16 + (lane >> 2);
    #pragma unroll
    for (int nt2 = 0; nt2 < 16; nt2++) {
        int col = h * HDD + nt2 * 8 + 2 * (lane & 3);
        size_t i0 = (size_t)(b * TT + row0) * DD + col;
        size_t i1 = (size_t)(b * TT + row0 + 8) * DD + col;
        uint32_t hp, lp;
        pack_hilo(oacc[nt2][0] * inv0, oacc[nt2][1] * inv0, hp, lp);
        *(uint32_t*)&g_ahi[i0] = hp; *(uint32_t*)&g_alo[i0] = lp;
        pack_hilo(oacc[nt2][2] * inv1, oacc[nt2][3] * inv1, hp, lp);
        *(uint32_t*)&g_ahi[i1] = hp; *(uint32_t*)&g_alo[i1] = lp;
    }
}

// ---------------- launch ----------------
extern "C" void kernel_launch(void* const* d_in, const int* in_sizes, int n_in,
                              void* d_out, int out_size)
{
    const float* x    = (const float*)d_in[0];
    const float* cosT = (const float*)d_in[1];
    const float* sinT = (const float*)d_in[2];
    const float* Wqkv = (const float*)d_in[3];
    const float* Wout = (const float*)d_in[4];
    float* out = (float*)d_out;

    float* qkv_p;
    cudaGetSymbolAddress((void**)&qkv_p, g_qkv);
    __nv_bfloat16 *xhi, *xlo, *wqh, *wql, *woh, *wol, *ahi, *alo;
    cudaGetSymbolAddress((void**)&xhi, g_xhi);
    cudaGetSymbolAddress((void**)&xlo, g_xlo);
    cudaGetSymbolAddress((void**)&wqh, g_wqh);
    cudaGetSymbolAddress((void**)&wql, g_wql);
    cudaGetSymbolAddress((void**)&woh, g_woh);
    cudaGetSymbolAddress((void**)&wol, g_wol);
    cudaGetSymbolAddress((void**)&ahi, g_ahi);
    cudaGetSymbolAddress((void**)&alo, g_alo);

    cudaFuncSetAttribute(gemm_bf16s, cudaFuncAttributeMaxDynamicSharedMemorySize, GEMM_SMEM);
    cudaFuncSetAttribute(flash_mma, cudaFuncAttributeMaxDynamicSharedMemorySize, FLASH2_SMEM);

    // 0) fused bf16 hi/lo splits of x, Wqkv, Wout
    {
        int total = MROWS * DD / 4 + 3 * DD * DD / 4 + DD * DD / 4;
        split3_bf16<<<(total + 255) / 256, 256>>>(x, Wqkv, Wout,
                                                  xhi, xlo, wqh, wql, woh, wol);
    }

    // 1) QKV projection (tensor cores)
    gemm_bf16s<<<dim3(3 * DD / 128, MROWS / 128), 256, GEMM_SMEM>>>(
        xhi, xlo, wqh, wql, qkv_p, MROWS, 3 * DD, DD);

    // 2) RoPE + bf16 hi/lo split of q,k,v (q pre-scaled by 1/sqrt(128)*log2e)
    rope_split<<<BB * TT * HH, HDD>>>(qkv_p, cosT, sinT);

    // 3) causal flash attention (tensor cores), writes g_ahi/g_alo
    flash_mma<<<dim3(TT / FQ2, HH, BB), 256, FLASH2_SMEM>>>();

    // 4) output projection (tensor cores)
    gemm_bf16s<<<dim3(DD / 128, MROWS / 128), 256, GEMM_SMEM>>>(
        ahi, alo, woh, wol, out, MROWS, DD, DD);
}